// round 11
// baseline (speedup 1.0000x reference)
#include <cuda_runtime.h>
#include <cstdint>

// RandomShiftsAug == integer pixel shift with edge clamp (reference's bilinear
// weights are exactly zero given its linspace/scale arithmetic):
//   out[n,c,j,i] = x[n,c, clamp(j+sy-PAD,0,H-1), clamp(i+sx-PAD,0,W-1)]
//
// R11 = R3 (SMEM stage + swizzle, best at 41.1us) with two changes driven by
// the LTS-cap model (all kernels plateau at DRAM~61% while ~410MB of LTS
// sector work runs at the ~11TB/s path-independent cap):
//  1. st.global.cs streaming stores: output no longer evicts the 115.6MB
//     input from the 126MB L2 across graph replays -> ~64MB of DRAM re-fill
//     (and its LTS DRAM-side work) disappears.
//  2. pad-fill fused into the load phase (edge-quad loader threads write the
//     clamp pads from registers) -> one less __syncthreads + no phase 2.

#define C_   4
#define W_   84
#define H_   84
#define PAD_ 4
#define W4_  21
#define RP_  96          // padded row: [0..3] pad | [4..87] data | [88..91] pad
#define NBLK (H_ * W4_)  // 1764 float4 per plane

__device__ __forceinline__ void stcs4(float4* p, float4 v) {
    asm volatile("st.global.cs.v4.f32 [%0], {%1, %2, %3, %4};"
                 :: "l"(p), "f"(v.x), "f"(v.y), "f"(v.z), "f"(v.w) : "memory");
}

__global__ void __launch_bounds__(256) shift_smem_kernel(
    const float* __restrict__ x,
    const int*   __restrict__ shift,
    float*       __restrict__ out)
{
    __shared__ float s[H_ * RP_];   // 32256 B

    const int nc  = blockIdx.x;     // n*C + c
    const int n   = nc >> 2;
    const int tid = threadIdx.x;

    int2 sh = __ldg(reinterpret_cast<const int2*>(shift) + n);
    const int sx = sh.x - PAD_;     // [-4, 4]
    const int sy = sh.y - PAD_;

    // ---- phase 1: coalesced stage GMEM -> SMEM, pads fused ----
    const float4* in4 = reinterpret_cast<const float4*>(x) + nc * NBLK;
    #pragma unroll
    for (int it = 0; it < 7; ++it) {
        int m = tid + it * 256;
        if (m < NBLK) {
            int row = m / W4_;
            int w4  = m - row * W4_;
            float4 v = __ldg(in4 + m);
            float4* prow = reinterpret_cast<float4*>(&s[row * RP_]);
            prow[w4 + 1] = v;                             // data at floats 4..87
            if (w4 == 0)        prow[0]  = make_float4(v.x, v.x, v.x, v.x);
            else if (w4 == 20)  prow[22] = make_float4(v.w, v.w, v.w, v.w);
        }
    }
    __syncthreads();

    // ---- phase 2: swizzle from SMEM, streaming coalesced stores ----
    float4* out4 = reinterpret_cast<float4*>(out) + nc * NBLK;
    #pragma unroll
    for (int it = 0; it < 7; ++it) {
        int m = tid + it * 256;
        if (m < NBLK) {
            int j  = m / W4_;
            int w4 = m - j * W4_;

            int ys = min(max(j + sy, 0), H_ - 1);
            int pp = 4 + w4 * 4 + sx;      // [0, 88]
            int q  = pp >> 2;
            int r  = pp & 3;               // warp-uniform (sx uniform per image)

            const float4* row4 = reinterpret_cast<const float4*>(&s[ys * RP_]);
            float4 A = row4[q];
            float4 v;
            if (r == 0) {
                v = A;
            } else {
                float4 B = row4[q + 1];
                if (r == 1)      v = make_float4(A.y, A.z, A.w, B.x);
                else if (r == 2) v = make_float4(A.z, A.w, B.x, B.y);
                else             v = make_float4(A.w, B.x, B.y, B.z);
            }
            stcs4(out4 + m, v);
        }
    }
}

extern "C" void kernel_launch(void* const* d_in, const int* in_sizes, int n_in,
                              void* d_out, int out_size)
{
    const float* x     = (const float*)d_in[0];
    const int*   shift = (const int*)d_in[1];
    float*       out   = (float*)d_out;

    int n = in_sizes[0] / (C_ * H_ * W_);
    shift_smem_kernel<<<n * C_, 256>>>(x, shift, out);
}